// round 16
// baseline (speedup 1.0000x reference)
#include <cuda_runtime.h>
#include <cuda_bf16.h>
#include <math.h>
#include <stdint.h>

#define E_N   4096
#define H_N   512
#define NH_N  4
#define HD_N  128
#define FFN_N 1024
#define H3_N  1536

// ---------------- fp32 scratch ----------------
__device__ float g_agg [E_N * H_N];
__device__ float g_gi  [E_N * H3_N];
__device__ float g_gh  [E_N * H3_N];
__device__ float g_h   [E_N * H_N];
__device__ float g_yprj[E_N * H_N];
__device__ int   g_idx64_flag;

// ---------------- packed bf16x2 hi/lo planes ----------------
__device__ uint32_t g_xhi   [E_N * 256], g_xlo   [E_N * 256];
__device__ uint32_t g_agghi [E_N * 256], g_agglo [E_N * 256];
__device__ uint32_t g_hhi   [E_N * 256], g_hlo   [E_N * 256];
__device__ uint32_t g_attnhi[E_N * 256], g_attnlo[E_N * 256];
__device__ uint32_t g_ynhi  [E_N * 256], g_ynlo  [E_N * 256];
__device__ uint32_t g_gacthi[E_N * 256], g_gactlo[E_N * 256];
#define WOFF_MSG  0
#define WOFF_IH   131072
#define WOFF_HH   524288
#define WOFF_INP  917504
#define WOFF_OUTP 1310720
#define WOFF_LIN  1441792
#define WOFF_F1   1572864
#define WTOTAL    1835008
__device__ uint32_t g_whi[WTOTAL], g_wlo[WTOTAL];
__device__ uint32_t g_qhi[NH_N * E_N * 64], g_qlo[NH_N * E_N * 64];
__device__ uint32_t g_khi[NH_N * E_N * 64], g_klo[NH_N * E_N * 64];
__device__ uint32_t g_vhi[NH_N * E_N * 64], g_vlo[NH_N * E_N * 64];

// ================= helpers =================
__device__ __forceinline__ uint32_t smem_u32(const void* p) {
    uint32_t a;
    asm("{ .reg .u64 t; cvta.to.shared.u64 t, %1; cvt.u32.u64 %0, t; }"
        : "=r"(a) : "l"(p));
    return a;
}

__device__ __forceinline__ void pack2(float x, float y, uint32_t& hi, uint32_t& lo) {
    __nv_bfloat162 h = __floats2bfloat162_rn(x, y);
    float hx = __bfloat162float(__low2bfloat16(h));
    float hy = __bfloat162float(__high2bfloat16(h));
    __nv_bfloat162 l = __floats2bfloat162_rn(x - hx, y - hy);
    hi = *reinterpret_cast<uint32_t*>(&h);
    lo = *reinterpret_cast<uint32_t*>(&l);
}

__device__ __forceinline__ void mma_bf16(float* d, const uint32_t* a, const uint32_t* b) {
    asm volatile(
        "mma.sync.aligned.m16n8k16.row.col.f32.bf16.bf16.f32 "
        "{%0,%1,%2,%3}, {%4,%5,%6,%7}, {%8,%9}, {%0,%1,%2,%3};"
        : "+f"(d[0]), "+f"(d[1]), "+f"(d[2]), "+f"(d[3])
        : "r"(a[0]), "r"(a[1]), "r"(a[2]), "r"(a[3]),
          "r"(b[0]), "r"(b[1]));
}

__device__ __forceinline__ void ldm_x4(uint32_t* r, uint32_t addr) {
    asm volatile("ldmatrix.sync.aligned.m8n8.x4.shared.b16 {%0,%1,%2,%3}, [%4];"
        : "=r"(r[0]), "=r"(r[1]), "=r"(r[2]), "=r"(r[3]) : "r"(addr));
}
__device__ __forceinline__ void ldm_x4t(uint32_t* r, uint32_t addr) {
    asm volatile("ldmatrix.sync.aligned.m8n8.x4.trans.shared.b16 {%0,%1,%2,%3}, [%4];"
        : "=r"(r[0]), "=r"(r[1]), "=r"(r[2]), "=r"(r[3]) : "r"(addr));
}

__device__ __forceinline__ void cpasync16(uint32_t saddr, const void* g) {
    asm volatile("cp.async.cg.shared.global [%0], [%1], 16;" :: "r"(saddr), "l"(g));
}
#define CP_COMMIT() asm volatile("cp.async.commit_group;" ::: "memory")
#define CP_WAIT0()  asm volatile("cp.async.wait_group 0;" ::: "memory")

// ================= bf16x3 GEMM body, 128x128 tiles =======================
#define WSTR 20
#define CH_WORDS (128 * WSTR)
#define GEMM_SMEM_BYTES (2 * 4 * CH_WORDS * 4)   // 81920

// EPI: 0 fp32 | 2 packed+relu | 3 relu+scatter | 4 relu+dot->atomic | 5 qkv planes
template <int EPI>
__device__ __forceinline__ void gemm_body(
    const uint32_t* __restrict__ Ahi, const uint32_t* __restrict__ Alo,
    const uint32_t* __restrict__ Bhi, const uint32_t* __restrict__ Blo,
    const float* __restrict__ bias,
    float* __restrict__ C, uint32_t* __restrict__ Chi, uint32_t* __restrict__ Clo,
    const void* __restrict__ ei, const float* __restrict__ w2,
    int N, int K, int bm, int bn, uint32_t sb)
{
    const int tid  = threadIdx.x;
    const int lane = tid & 31;
    const int wid  = tid >> 5;
    const int wm64 = (wid >> 2) << 6;
    const int wn32 = (wid & 3) << 5;
    const int Kw = K >> 1;
    const int NKC = K >> 5;

    float acc[4][4][4];
#pragma unroll
    for (int mt = 0; mt < 4; mt++)
#pragma unroll
        for (int nt = 0; nt < 4; nt++)
#pragma unroll
            for (int c = 0; c < 4; c++) acc[mt][nt][c] = 0.f;

    auto stage = [&](int kc, int buf) {
        const uint32_t base = (uint32_t)buf * (4 * CH_WORDS);
        const int kcw = kc << 4;
#pragma unroll
        for (int j = 0; j < 2; j++) {
            int idx = tid + (j << 8);
            int r = idx >> 2, w4 = (idx & 3) << 2;
            uint32_t so = base + (uint32_t)(r * WSTR + w4);
            size_t ga = (size_t)(bm + r) * Kw + kcw + w4;
            size_t gb = (size_t)(bn + r) * Kw + kcw + w4;
            cpasync16(sb + (so << 2),                  Ahi + ga);
            cpasync16(sb + ((so + CH_WORDS) << 2),     Alo + ga);
            cpasync16(sb + ((so + 2 * CH_WORDS) << 2), Bhi + gb);
            cpasync16(sb + ((so + 3 * CH_WORDS) << 2), Blo + gb);
        }
    };

    stage(0, 0);
    CP_COMMIT();

    for (int kc = 0; kc < NKC; kc++) {
        CP_WAIT0();
        __syncthreads();
        if (kc + 1 < NKC) {
            stage(kc + 1, (kc + 1) & 1);
            CP_COMMIT();
        }
        const uint32_t bb = (uint32_t)(kc & 1) * (4 * CH_WORDS);
#pragma unroll
        for (int ks = 0; ks < 2; ks++) {
            const int kw = ks << 3;
            uint32_t ahi[4][4], alo[4][4];
#pragma unroll
            for (int mt = 0; mt < 4; mt++) {
                uint32_t wo = bb + (uint32_t)((wm64 + (mt << 4) + (lane & 15)) * WSTR
                                              + kw + ((lane >> 4) << 2));
                ldm_x4(ahi[mt], sb + (wo << 2));
                ldm_x4(alo[mt], sb + ((wo + CH_WORDS) << 2));
            }
            uint32_t bhi[4][2], blo[4][2];
#pragma unroll
            for (int np = 0; np < 2; np++) {
                uint32_t wo = bb + (uint32_t)((wn32 + (np << 4) + (((lane >> 4) & 1) << 3)
                                               + (lane & 7)) * WSTR
                                              + kw + (((lane >> 3) & 1) << 2));
                uint32_t r4[4];
                ldm_x4(r4, sb + ((wo + 2 * CH_WORDS) << 2));
                bhi[2 * np][0] = r4[0]; bhi[2 * np][1] = r4[1];
                bhi[2 * np + 1][0] = r4[2]; bhi[2 * np + 1][1] = r4[3];
                ldm_x4(r4, sb + ((wo + 3 * CH_WORDS) << 2));
                blo[2 * np][0] = r4[0]; blo[2 * np][1] = r4[1];
                blo[2 * np + 1][0] = r4[2]; blo[2 * np + 1][1] = r4[3];
            }
#pragma unroll
            for (int mt = 0; mt < 4; mt++)
#pragma unroll
                for (int nt = 0; nt < 4; nt++)
                    mma_bf16(acc[mt][nt], ahi[mt], bhi[nt]);
#pragma unroll
            for (int mt = 0; mt < 4; mt++)
#pragma unroll
                for (int nt = 0; nt < 4; nt++)
                    mma_bf16(acc[mt][nt], ahi[mt], blo[nt]);
#pragma unroll
            for (int mt = 0; mt < 4; mt++)
#pragma unroll
                for (int nt = 0; nt < 4; nt++)
                    mma_bf16(acc[mt][nt], alo[mt], bhi[nt]);
        }
    }

    uint32_t *DH = nullptr, *DL = nullptr;
    float epi5_scale = 1.f;
    int epi5_head = 0;
    if (EPI == 5) {
        int which = bn >> 9;
        epi5_head = (bn >> 7) & 3;
        DH = (which == 0) ? g_qhi : (which == 1) ? g_khi : g_vhi;
        DL = (which == 0) ? g_qlo : (which == 1) ? g_klo : g_vlo;
        if (which == 0) epi5_scale = 0.08838834764831845f;
    }

#pragma unroll
    for (int mt = 0; mt < 4; mt++) {
        int row0 = bm + wm64 + (mt << 4) + (lane >> 2);
        int dst0 = 0, dst1 = 0;
        if (EPI == 3) {
            if (g_idx64_flag) {
                dst0 = (int)((const long long*)ei)[E_N + row0];
                dst1 = (int)((const long long*)ei)[E_N + row0 + 8];
            } else {
                dst0 = ((const int*)ei)[E_N + row0];
                dst1 = ((const int*)ei)[E_N + row0 + 8];
            }
            if ((unsigned)dst0 >= (unsigned)E_N) dst0 = 0;
            if ((unsigned)dst1 >= (unsigned)E_N) dst1 = 0;
        }
        float prow0 = 0.f, prow1 = 0.f;
#pragma unroll
        for (int nt = 0; nt < 4; nt++) {
            int col0 = bn + wn32 + (nt << 3) + ((lane & 3) << 1);
            float b0 = bias[col0], b1 = bias[col0 + 1];
            float v00 = acc[mt][nt][0] + b0, v01 = acc[mt][nt][1] + b1;
            float v10 = acc[mt][nt][2] + b0, v11 = acc[mt][nt][3] + b1;
            if (EPI >= 1 && EPI != 5) {
                v00 = fmaxf(v00, 0.f); v01 = fmaxf(v01, 0.f);
                v10 = fmaxf(v10, 0.f); v11 = fmaxf(v11, 0.f);
            }
            if (EPI == 5) {
                v00 *= epi5_scale; v01 *= epi5_scale;
                v10 *= epi5_scale; v11 *= epi5_scale;
                int dw = (col0 & 127) >> 1;
                size_t d0 = ((size_t)epi5_head * E_N + row0) * 64 + dw;
                uint32_t h, l;
                pack2(v00, v01, h, l);
                DH[d0] = h; DL[d0] = l;
                pack2(v10, v11, h, l);
                DH[d0 + 8 * 64] = h; DL[d0 + 8 * 64] = l;
            } else if (EPI == 4) {
                float w0 = w2[col0], w1 = w2[col0 + 1];
                prow0 += v00 * w0 + v01 * w1;
                prow1 += v10 * w0 + v11 * w1;
            } else if (EPI == 3) {
                float* a0 = g_agg + (size_t)dst0 * H_N + col0;
                float* a1 = g_agg + (size_t)dst1 * H_N + col0;
                atomicAdd(a0,     v00); atomicAdd(a0 + 1, v01);
                atomicAdd(a1,     v10); atomicAdd(a1 + 1, v11);
            } else if (EPI == 2) {
                int Nw = N >> 1;
                uint32_t h, l;
                pack2(v00, v01, h, l);
                Chi[(size_t)row0 * Nw + (col0 >> 1)] = h;
                Clo[(size_t)row0 * Nw + (col0 >> 1)] = l;
                pack2(v10, v11, h, l);
                Chi[(size_t)(row0 + 8) * Nw + (col0 >> 1)] = h;
                Clo[(size_t)(row0 + 8) * Nw + (col0 >> 1)] = l;
            } else {
                *(float2*)(C + (size_t)row0 * N + col0) = make_float2(v00, v01);
                *(float2*)(C + (size_t)(row0 + 8) * N + col0) = make_float2(v10, v11);
            }
        }
        if (EPI == 4) {
            prow0 += __shfl_xor_sync(0xffffffffu, prow0, 1);
            prow0 += __shfl_xor_sync(0xffffffffu, prow0, 2);
            prow1 += __shfl_xor_sync(0xffffffffu, prow1, 1);
            prow1 += __shfl_xor_sync(0xffffffffu, prow1, 2);
            if ((lane & 3) == 0) {
                atomicAdd(C + row0, prow0);
                atomicAdd(C + row0 + 8, prow1);
            }
        }
    }
}

template <int EPI>
__global__ __launch_bounds__(256, 2) void gemm_pk(
    const uint32_t* __restrict__ Ahi, const uint32_t* __restrict__ Alo,
    const uint32_t* __restrict__ Bhi, const uint32_t* __restrict__ Blo,
    const float* __restrict__ bias,
    float* __restrict__ C, uint32_t* __restrict__ Chi, uint32_t* __restrict__ Clo,
    const void* __restrict__ ei, const float* __restrict__ w2, int N, int K)
{
    extern __shared__ uint32_t smw[];
    gemm_body<EPI>(Ahi, Alo, Bhi, Blo, bias, C, Chi, Clo, ei, w2, N, K,
                   blockIdx.y << 7, blockIdx.x << 7, smem_u32(smw));
}

__global__ __launch_bounds__(256, 2) void gemm_dual(
    const uint32_t* __restrict__ Ahi, const uint32_t* __restrict__ Alo,
    const uint32_t* __restrict__ B1hi, const uint32_t* __restrict__ B1lo,
    const float* __restrict__ bias1, float* __restrict__ C1,
    const uint32_t* __restrict__ B2hi, const uint32_t* __restrict__ B2lo,
    const float* __restrict__ bias2, const void* __restrict__ ei, int K)
{
    extern __shared__ uint32_t smw[];
    const uint32_t sb = smem_u32(smw);
    const int bm = blockIdx.y << 7;
    if (blockIdx.x < 12)
        gemm_body<0>(Ahi, Alo, B1hi, B1lo, bias1, C1, nullptr, nullptr, nullptr, nullptr,
                     H3_N, K, bm, blockIdx.x << 7, sb);
    else
        gemm_body<3>(Ahi, Alo, B2hi, B2lo, bias2, nullptr, nullptr, nullptr, ei, nullptr,
                     H_N, K, bm, (blockIdx.x - 12) << 7, sb);
}

// ---------------- prep ----------------
// blocks: [0,1792) weights | [1792,2816) x | [2816,4864) zero agg v4 | [4864,4880) out
__global__ __launch_bounds__(256) void prep_kernel(
    const float* __restrict__ x, const int* __restrict__ ei32,
    const float* __restrict__ w0, const float* __restrict__ w1,
    const float* __restrict__ w2, const float* __restrict__ w3,
    const float* __restrict__ w4, const float* __restrict__ w5,
    const float* __restrict__ w6,
    float* __restrict__ out, const float* __restrict__ b2)
{
    int b = blockIdx.x;
    if (b < 1792) {
        int i = b * 256 + threadIdx.x;
        const unsigned char segtab[14] = {0,1,1,1,2,2,2,3,3,3,4,5,6,6};
        const int segbase[7] = {0, 32768, 131072, 229376, 327680, 360448, 393216};
        int unit = i >> 15;
        int seg = segtab[unit];
        int li = i - segbase[seg];
        const float* src;
        switch (seg) {
            case 0: src = w0; break;
            case 1: src = w1; break;
            case 2: src = w2; break;
            case 3: src = w3; break;
            case 4: src = w4; break;
            case 5: src = w5; break;
            default: src = w6; break;
        }
        float4 a = *(const float4*)(src + (size_t)li * 8);
        float4 c = *(const float4*)(src + (size_t)li * 8 + 4);
        uint4 h, l;
        pack2(a.x, a.y, h.x, l.x);
        pack2(a.z, a.w, h.y, l.y);
        pack2(c.x, c.y, h.z, l.z);
        pack2(c.z, c.w, h.w, l.w);
        *(uint4*)(g_whi + (size_t)i * 4) = h;
        *(uint4*)(g_wlo + (size_t)i * 4) = l;
    } else if (b < 2816) {
        int i = (b - 1792) * 256 + threadIdx.x;
        float4 a = *(const float4*)(x + (size_t)i * 8);
        float4 c = *(const float4*)(x + (size_t)i * 8 + 4);
        uint4 h, l;
        pack2(a.x, a.y, h.x, l.x);
        pack2(a.z, a.w, h.y, l.y);
        pack2(c.x, c.y, h.z, l.z);
        pack2(c.z, c.w, h.w, l.w);
        *(uint4*)(g_xhi + (size_t)i * 4) = h;
        *(uint4*)(g_xlo + (size_t)i * 4) = l;
    } else if (b < 4864) {
        int i = (b - 2816) * 256 + threadIdx.x;
        *(float4*)(g_agg + (size_t)i * 4) = make_float4(0.f, 0.f, 0.f, 0.f);
        if (i == 0) {
            int allzero = 1;
#pragma unroll
            for (int k = 1; k < 16; k += 2)
                if (ei32[k] != 0) allzero = 0;
            g_idx64_flag = allzero;
        }
    } else {
        int i = (b - 4864) * 256 + threadIdx.x;
        out[i] = b2[0];
    }
}

// ---------------- vectorized pair-split (agg) ----------------
__global__ __launch_bounds__(256) void split_pairs_v4(
    const float* __restrict__ src, uint32_t* __restrict__ hi,
    uint32_t* __restrict__ lo, int ngroups)
{
    int i = blockIdx.x * 256 + threadIdx.x;
    if (i >= ngroups) return;
    float4 a = *(const float4*)(src + (size_t)i * 8);
    float4 b = *(const float4*)(src + (size_t)i * 8 + 4);
    uint4 h, l;
    pack2(a.x, a.y, h.x, l.x);
    pack2(a.z, a.w, h.y, l.y);
    pack2(b.x, b.y, h.z, l.z);
    pack2(b.z, b.w, h.w, l.w);
    *(uint4*)(hi + (size_t)i * 4) = h;
    *(uint4*)(lo + (size_t)i * 4) = l;
}

// ---------------- GRU elementwise (+ h planes) ----------------
__global__ __launch_bounds__(256) void gru_kernel(const float* __restrict__ x) {
    int idx = blockIdx.x * 256 + threadIdx.x;
    if (idx >= E_N * 256) return;
    int e = idx >> 8, i = (idx & 255) << 1;
    const float* gi = g_gi + (size_t)e * H3_N;
    const float* gh = g_gh + (size_t)e * H3_N;
    float h2[2];
#pragma unroll
    for (int u = 0; u < 2; u++) {
        int c = i + u;
        float r = 1.f / (1.f + __expf(-(gi[c] + gh[c])));
        float z = 1.f / (1.f + __expf(-(gi[H_N + c] + gh[H_N + c])));
        float n = tanhf(gi[2 * H_N + c] + r * gh[2 * H_N + c]);
        h2[u] = (1.f - z) * n + z * x[(size_t)e * H_N + c];
        g_h[(size_t)e * H_N + c] = h2[u];
    }
    uint32_t h, l;
    pack2(h2[0], h2[1], h, l);
    g_hhi[idx] = h; g_hlo[idx] = l;
}

// ---------------- flash-attention v2: 64 q-rows, 4 warps, BC=32 ----------
#define ATQ_STR 68
#define ATQ_WORDS (64 * ATQ_STR)           // 4352 per plane
#define ATK_WORDS (32 * ATQ_STR)           // 2176 per plane (K and V)
#define AT_KV0 (2 * ATQ_WORDS)             // 8704
#define KVBUF_WORDS (4 * ATK_WORDS)        // 8704
#define ATTN_SMEM_BYTES ((AT_KV0 + 2 * KVBUF_WORDS) * 4)  // 104448

__global__ __launch_bounds__(128) void attn_bf16_kernel() {
    extern __shared__ uint32_t smw[];
    const uint32_t sb = smem_u32(smw);

    const int t = threadIdx.x;
    const int lane = t & 31;
    const int w = t >> 5;                    // 0..3, warp owns rows w*16..+15
    const int q0 = blockIdx.x << 6;          // 64 q-rows per CTA
    const int head = blockIdx.y;

    // Q tile: 64 rows x 16 uint4 per plane; 128 threads x 8 iters
    {
        size_t qb = ((size_t)head * E_N + q0) * 64;
#pragma unroll
        for (int j = 0; j < 8; j++) {
            int i = t + (j << 7);
            int r = i >> 4, w4 = (i & 15) << 2;
            *(uint4*)(smw + r * ATQ_STR + w4) = *(const uint4*)&g_qhi[qb + r * 64 + w4];
            *(uint4*)(smw + ATQ_WORDS + r * ATQ_STR + w4) = *(const uint4*)&g_qlo[qb + r * 64 + w4];
        }
    }

    auto stage_kv = [&](int j0, int buf) {
        const uint32_t base = AT_KV0 + (uint32_t)buf * KVBUF_WORDS;
        size_t kb = ((size_t)head * E_N + j0) * 64;
#pragma unroll
        for (int j = 0; j < 4; j++) {
            int i = t + (j << 7);
            int r = i >> 4, w4 = (i & 15) << 2;
            uint32_t so = base + (uint32_t)(r * ATQ_STR + w4);
            cpasync16(sb + (so << 2),                   g_khi + kb + r * 64 + w4);
            cpasync16(sb + ((so + ATK_WORDS) << 2),     g_klo + kb + r * 64 + w4);
            cpasync16(sb + ((so + 2 * ATK_WORDS) << 2), g_vhi + kb + r * 64 + w4);
            cpasync16(sb + ((so + 3 * ATK_WORDS) << 2), g_vlo + kb + r * 64 + w4);
        }
    };

    stage_kv(0, 0);
    CP_COMMIT();

    float o[16][4];
#pragma unroll
    for (int nf = 0; nf < 16; nf++)
#pragma unroll
        for (int c = 0; c < 4; c++) o[nf][c] = 0.f;
    float m0 = -1e30f, m1 = -1e30f, l0 = 0.f, l1 = 0.f;

    int buf = 0;
    for (int j0 = 0; j0 < E_N; j0 += 32) {
        CP_WAIT0();
        __syncthreads();
        if (j0 + 32 < E_N) {
            stage_kv(j0 + 32, buf ^ 1);
            CP_COMMIT();
        }
        const uint32_t kvb = AT_KV0 + (uint32_t)buf * KVBUF_WORDS;

        // ---- S = Q K^T (bf16x3): 32 j-cols, sacc[4][4] ----
        float sacc[4][4];
#pragma unroll
        for (int nf = 0; nf < 4; nf++)
#pragma unroll
            for (int c = 0; c < 4; c++) sacc[nf][c] = 0.f;

#pragma unroll
        for (int ks = 0; ks < 8; ks++) {
            const int kw = ks << 3;
            uint32_t ahi[4], alo[4];
            uint32_t ao = (uint32_t)((((w << 4) + (lane & 15)) * ATQ_STR
                                      + kw + ((lane >> 4) << 2)) << 2);
            ldm_x4(ahi, sb + ao);
            ldm_x4(alo, sb + ao + (ATQ_WORDS << 2));
#pragma unroll
            for (int np = 0; np < 2; np++) {
                uint32_t bo = (uint32_t)((kvb + ((np << 4) + (((lane >> 4) & 1) << 3)
                                                 + (lane & 7)) * ATQ_STR
                                          + kw + (((lane >> 3) & 1) << 2)) << 2);
                uint32_t bh4[4], bl4[4];
                ldm_x4(bh4, sb + bo);
                ldm_x4(bl4, sb + bo + (ATK_WORDS << 2));
                mma_bf16(sacc[2 * np],     ahi, bh4);
                mma_bf16(sacc[2 * np],     ahi, bl4);
                mma_bf16(sacc[2 * np],     alo, bh4);
                mma_bf16(sacc[2 * np + 1], ahi, bh4 + 2);
                mma_bf16(sacc[2 * np + 1], ahi, bl4 + 2);
                mma_bf16(sacc[2 * np + 1], alo, bh4 + 2);
            }
        }

        // ---- register online softmax ----
        float mloc0 = -1e30f, mloc1 = -1e30f;
#pragma unroll
        for (int nf = 0; nf < 4; nf++) {
            mloc0 = fmaxf(mloc0, fmaxf(sacc[nf][0], sacc[nf][1]));
            mloc1 = fmaxf(mloc1, fmaxf(sacc[nf][2], sacc[nf][3]));
        }
        mloc0 = fmaxf(mloc0, __shfl_xor_sync(0xffffffffu, mloc0, 1));
        mloc0 = fmaxf(mloc0, __shfl_xor_sync(0xffffffffu, mloc0, 2));
        mloc1 = fmaxf(mloc1, __shfl_xor_sync(0xffffffffu, mloc1, 1));
        mloc1 = fmaxf(mloc1, __shfl_xor_sync(0xffffffffu, mloc1, 2));
        float mnew0 = fmaxf(m0, mloc0), mnew1 = fmaxf(m1, mloc1);
        float alpha0 = __expf(m0 - mnew0), alpha1 = __expf(m1 - mnew1);
        float s0 = 0.f, s1 = 0.f;
#pragma unroll
        for (int nf = 0; nf < 4; nf++) {
            sacc[nf][0] = __expf(sacc[nf][0] - mnew0);
            sacc[nf][1] = __expf(sacc[nf][1] - mnew0);
            sacc[nf][2] = __expf(sacc[nf][2] - mnew1);
            sacc[nf][3] = __expf(sacc[nf][3] - mnew1);
            s0 += sacc[nf][0] + sacc[nf][1];
            s1 += sacc[nf][2] + sacc[nf][3];
        }
        s0 += __shfl_xor_sync(0xffffffffu, s0, 1);
        s0 += __shfl_xor_sync(0xffffffffu, s0, 2);
        s1 += __shfl_xor_sync(0xffffffffu, s1, 1);
        s1 += __shfl_xor_sync(0xffffffffu, s1, 2);
        l0 = l0 * alpha0 + s0;  m0 = mnew0;
        l1 = l1 * alpha1 + s1;  m1 = mnew1;
#pragma unroll
        for (int nf = 0; nf < 16; nf++) {
            o[nf][0] *= alpha0; o[nf][1] *= alpha0;
            o[nf][2] *= alpha1; o[nf][3] *= alpha1;
        }

        // ---- O += P V; trans-V frags; ks 0..1 over 32 j ----
#pragma unroll
        for (int ks = 0; ks < 2; ks++) {
            uint32_t phi[4], plo[4];
            pack2(sacc[2 * ks][0],     sacc[2 * ks][1],     phi[0], plo[0]);
            pack2(sacc[2 * ks][2],     sacc[2 * ks][3],     phi[1], plo[1]);
            pack2(sacc[2 * ks + 1][0], sacc[2 * ks + 1][1], phi[2], plo[2]);
            pack2(sacc[2 * ks + 1][2], sacc[2 * ks + 1][3], phi[3], plo[3]);
#pragma unroll
            for (int np = 0; np < 8; np++) {
                uint32_t bo = (uint32_t)((kvb + 2 * ATK_WORDS
                                          + ((ks << 4) + (lane & 15)) * ATQ_STR
                                          + (np << 3) + ((lane >> 4) << 2)) << 2);
                uint32_t bh4[4], bl4[4];
                ldm_x4t(bh4, sb + bo);
                ldm_x4t(bl4, sb + bo + (ATK_WORDS << 2));
                mma_bf16(o[2 * np],     phi, bh4);
                mma_bf16(o[2 * np],     phi, bl4);
                mma_bf16(o[2 * np],     plo, bh4);
                mma_bf16(o[2 * np + 1], phi, bh4 + 2);
                mma_bf16(o[2 * np + 1], phi, bl4 + 2);
                mma_bf16(o[2 * np + 1], plo, bh4 + 2);
            }
        }
        buf ^= 1;
    }

    // ---- epilogue ----
    {
        const int gid = lane >> 2;
        const int qid = lane & 3;
        const int r0 = (w << 4) + gid;
        float inv0 = 1.f / l0;
        float inv1 = 1.f / l1;
#pragma unroll
        for (int nf = 0; nf < 16; nf++) {
            int cw = head * 64 + (nf << 2) + qid;
            uint32_t h, l;
            pack2(o[nf][0] * inv0, o[nf][1] * inv0, h, l);
            g_attnhi[(size_t)(q0 + r0) * 256 + cw] = h;
            g_attnlo[(size_t)(q0 + r0) * 256 + cw] = l;
            pack2(o[nf][2] * inv1, o[nf][3] * inv1, h, l);
            g_attnhi[(size_t)(q0 + r0 + 8) * 256 + cw] = h;
            g_attnlo[(size_t)(q0 + r0 + 8) * 256 + cw] = l;
        }
    }
}

// ---------------- residual + LayerNorm ----------------
__global__ __launch_bounds__(256) void ln_kernel(const float* __restrict__ ln_g,
                                                 const float* __restrict__ ln_b) {
    __shared__ float reda[8], redb[8];
    int e = blockIdx.x;
    int t = threadIdx.x;
    const float* yp = g_yprj + (size_t)e * H_N;
    const float* hp = g_h + (size_t)e * H_N;
    int i0 = t << 1, i1 = i0 + 1;
    float v0 = yp[i0] + hp[i0];
    float v1 = yp[i1] + hp[i1];
    float s = v0 + v1, s2 = v0 * v0 + v1 * v1;
#pragma unroll
    for (int o = 16; o > 0; o >>= 1) {
        s  += __shfl_down_sync(0xffffffffu, s, o);
        s2 += __shfl_down_sync(0xffffffffu, s2, o);
    }
    int w = t >> 5;
    if ((t & 31) == 0) { reda[w] = s; redb[w] = s2; }
    __syncthreads();
    if (t < 8) {
        s = reda[t]; s2 = redb[t];
#pragma unroll
        for (int o = 4; o > 0; o >>= 1) {
            s  += __shfl_down_sync(0xffu, s, o);
            s2 += __shfl_down_sync(0xffu, s2, o);
        }
        if (t == 0) { reda[0] = s; redb[0] = s2; }
    }
    __syncthreads();
    float mu = reda[0] * (1.f / H_N);
    float var = redb[0] * (1.f / H_N) - mu * mu;
    float rstd = rsqrtf(var + 1e-5f);
    float y0 = (v0 - mu) * rstd * ln_g[i0] + ln_b[i0];
    float y1 = (v1 - mu) * rstd * ln_g[i1] + ln_b[i1];
    uint32_t h, l;
    pack2(y0, y1, h, l);
    g_ynhi[(size_t)e * 256 + t] = h;
    g_ynlo[(size_t)e * 256 + t] = l;
}

// ---------------- launcher ----------------
extern "C" void kernel_launch(void* const* d_in, const int* in_sizes, int n_in,
                              void* d_out, int out_size) {
    const float* x       = (const float*)d_in[0];
    const void*  ei      = d_in[1];
    const float* W_msg   = (const float*)d_in[2];
    const float* b_msg   = (const float*)d_in[3];
    const float* W_ih    = (const float*)d_in[4];
    const float* b_ih    = (const float*)d_in[5];
    const float* W_hh    = (const float*)d_in[6];
    const float* b_hh    = (const float*)d_in[7];
    const float* W_inp   = (const float*)d_in[8];
    const float* b_inp   = (const float*)d_in[9];
    const float* W_outp  = (const float*)d_in[10];
    const float* b_outp  = (const float*)d_in[11];
    const float* ln_g    = (const float*)d_in[12];
    const float* ln_b    = (const float*)d_in[13];
    const float* W_lin   = (const float*)d_in[14];
    const float* b_lin   = (const float*)d_in[15];
    const float* W_f1    = (const float*)d_in[16];
    const float* b_f1    = (const float*)d_in[17];
    const float* W_f2    = (const float*)d_in[18];
    const float* b_f2    = (const float*)d_in[19];
    float* out = (float*)d_out;

    float *p_gi, *p_gh, *p_yprj, *p_agg;
    cudaGetSymbolAddress((void**)&p_agg,  g_agg);
    cudaGetSymbolAddress((void**)&p_gi,   g_gi);
    cudaGetSymbolAddress((void**)&p_gh,   g_gh);
    cudaGetSymbolAddress((void**)&p_yprj, g_yprj);
    uint32_t *p_xhi, *p_xlo, *p_agghi, *p_agglo, *p_hhi, *p_hlo;
    uint32_t *p_attnhi, *p_attnlo, *p_ynhi, *p_ynlo, *p_gacthi, *p_gactlo;
    uint32_t *p_whi, *p_wlo;
    cudaGetSymbolAddress((void**)&p_xhi,    g_xhi);
    cudaGetSymbolAddress((void**)&p_xlo,    g_xlo);
    cudaGetSymbolAddress((void**)&p_agghi,  g_agghi);
    cudaGetSymbolAddress((void**)&p_agglo,  g_agglo);
    cudaGetSymbolAddress((void**)&p_hhi,    g_hhi);
    cudaGetSymbolAddress((void**)&p_hlo,    g_hlo);
    cudaGetSymbolAddress((void**)&p_attnhi, g_attnhi);
    cudaGetSymbolAddress((void**)&p_attnlo, g_attnlo);
    cudaGetSymbolAddress((void**)&p_ynhi,   g_ynhi);
    cudaGetSymbolAddress((void**)&p_ynlo,   g_ynlo);
    cudaGetSymbolAddress((void**)&p_gacthi, g_gacthi);
    cudaGetSymbolAddress((void**)&p_gactlo, g_gactlo);
    cudaGetSymbolAddress((void**)&p_whi,    g_whi);
    cudaGetSymbolAddress((void**)&p_wlo,    g_wlo);

    cudaFuncSetAttribute(gemm_pk<0>, cudaFuncAttributeMaxDynamicSharedMemorySize, GEMM_SMEM_BYTES);
    cudaFuncSetAttribute(gemm_pk<2>, cudaFuncAttributeMaxDynamicSharedMemorySize, GEMM_SMEM_BYTES);
    cudaFuncSetAttribute(gemm_pk<4>, cudaFuncAttributeMaxDynamicSharedMemorySize, GEMM_SMEM_BYTES);
    cudaFuncSetAttribute(gemm_pk<5>, cudaFuncAttributeMaxDynamicSharedMemorySize, GEMM_SMEM_BYTES);
    cudaFuncSetAttribute(gemm_dual,  cudaFuncAttributeMaxDynamicSharedMemorySize, GEMM_SMEM_BYTES);
    cudaFuncSetAttribute(attn_bf16_kernel, cudaFuncAttributeMaxDynamicSharedMemorySize, ATTN_SMEM_BYTES);

    // 0) prep
    prep_kernel<<<4880, 256>>>(x, (const int*)ei, W_msg, W_ih, W_hh, W_inp,
                               W_outp, W_lin, W_f1, out, b_f2);
    // 1) merged gh + msg(scatter) GEMM
    gemm_dual<<<dim3(16, 32), 256, GEMM_SMEM_BYTES>>>(
        p_xhi, p_xlo,
        p_whi + WOFF_HH, p_wlo + WOFF_HH, b_hh, p_gh,
        p_whi + WOFF_MSG, p_wlo + WOFF_MSG, b_msg, ei, H_N);
    // 2) agg planes
    split_pairs_v4<<<(E_N * 64) / 256, 256>>>(p_agg, p_agghi, p_agglo, E_N * 64);
    // 3) gi   <-- profiled slot
    gemm_pk<0><<<dim3(H3_N / 128, 32), 256, GEMM_SMEM_BYTES>>>(
        p_agghi, p_agglo, p_whi + WOFF_IH, p_wlo + WOFF_IH, b_ih, p_gi,
        nullptr, nullptr, nullptr, nullptr, H3_N, H_N);
    // 4) GRU
    gru_kernel<<<(E_N * 256) / 256, 256>>>(x);
    // 5) qkv -> per-head Q/K/V planes (EPI5)
    gemm_pk<5><<<dim3(H3_N / 128, 32), 256, GEMM_SMEM_BYTES>>>(
        p_hhi, p_hlo, p_whi + WOFF_INP, p_wlo + WOFF_INP, b_inp, nullptr,
        nullptr, nullptr, nullptr, nullptr, H3_N, H_N);
    // 6) attention (64-row CTAs, 2/SM)
    attn_bf16_kernel<<<dim3(E_N / 64, NH_N), 128, ATTN_SMEM_BYTES>>>();
    // 7) out-proj
    gemm_pk<0><<<dim3(H_N / 128, 32), 256, GEMM_SMEM_BYTES>>>(
        p_attnhi, p_attnlo, p_whi + WOFF_OUTP, p_wlo + WOFF_OUTP, b_outp, p_yprj,
        nullptr, nullptr, nullptr, nullptr, H_N, H_N);
    // 8) residual + LN
    ln_kernel<<<E_N, 256>>>(ln_g, ln_b);
    // 9) g = relu(yn @ W_lin^T + b) -> packed
    gemm_pk<2><<<dim3(H_N / 128, 32), 256, GEMM_SMEM_BYTES>>>(
        p_ynhi, p_ynlo, p_whi + WOFF_LIN, p_wlo + WOFF_LIN, b_lin, nullptr,
        p_gacthi, p_gactlo, nullptr, nullptr, H_N, H_N);
    // 10) f = relu(g @ W_f1^T + b_f1) fused with final dot
    gemm_pk<4><<<dim3(FFN_N / 128, 32), 256, GEMM_SMEM_BYTES>>>(
        p_gacthi, p_gactlo, p_whi + WOFF_F1, p_wlo + WOFF_F1, b_f1, out,
        nullptr, nullptr, nullptr, W_f2, FFN_N, H_N);
}

// round 17
// speedup vs baseline: 1.0469x; 1.0469x over previous
#include <cuda_runtime.h>
#include <cuda_bf16.h>
#include <math.h>
#include <stdint.h>

#define E_N   4096
#define H_N   512
#define NH_N  4
#define HD_N  128
#define FFN_N 1024
#define H3_N  1536

// ---------------- fp32 scratch ----------------
__device__ float g_agg [E_N * H_N];
__device__ float g_gi  [E_N * H3_N];
__device__ float g_gh  [E_N * H3_N];
__device__ float g_h   [E_N * H_N];
__device__ float g_yprj[E_N * H_N];
__device__ int   g_idx64_flag;

// ---------------- packed bf16x2 hi/lo planes ----------------
__device__ uint32_t g_xhi   [E_N * 256], g_xlo   [E_N * 256];
__device__ uint32_t g_agghi [E_N * 256], g_agglo [E_N * 256];
__device__ uint32_t g_hhi   [E_N * 256], g_hlo   [E_N * 256];
__device__ uint32_t g_attnhi[E_N * 256], g_attnlo[E_N * 256];
__device__ uint32_t g_ynhi  [E_N * 256], g_ynlo  [E_N * 256];
__device__ uint32_t g_gacthi[E_N * 256], g_gactlo[E_N * 256];
#define WOFF_MSG  0
#define WOFF_IH   131072
#define WOFF_HH   524288
#define WOFF_INP  917504
#define WOFF_OUTP 1310720
#define WOFF_LIN  1441792
#define WOFF_F1   1572864
#define WTOTAL    1835008
__device__ uint32_t g_whi[WTOTAL], g_wlo[WTOTAL];
__device__ uint32_t g_qhi[NH_N * E_N * 64], g_qlo[NH_N * E_N * 64];
__device__ uint32_t g_khi[NH_N * E_N * 64], g_klo[NH_N * E_N * 64];
__device__ uint32_t g_vhi[NH_N * E_N * 64], g_vlo[NH_N * E_N * 64];

// ================= helpers =================
__device__ __forceinline__ uint32_t smem_u32(const void* p) {
    uint32_t a;
    asm("{ .reg .u64 t; cvta.to.shared.u64 t, %1; cvt.u32.u64 %0, t; }"
        : "=r"(a) : "l"(p));
    return a;
}

__device__ __forceinline__ void pack2(float x, float y, uint32_t& hi, uint32_t& lo) {
    __nv_bfloat162 h = __floats2bfloat162_rn(x, y);
    float hx = __bfloat162float(__low2bfloat16(h));
    float hy = __bfloat162float(__high2bfloat16(h));
    __nv_bfloat162 l = __floats2bfloat162_rn(x - hx, y - hy);
    hi = *reinterpret_cast<uint32_t*>(&h);
    lo = *reinterpret_cast<uint32_t*>(&l);
}

__device__ __forceinline__ void mma_bf16(float* d, const uint32_t* a, const uint32_t* b) {
    asm volatile(
        "mma.sync.aligned.m16n8k16.row.col.f32.bf16.bf16.f32 "
        "{%0,%1,%2,%3}, {%4,%5,%6,%7}, {%8,%9}, {%0,%1,%2,%3};"
        : "+f"(d[0]), "+f"(d[1]), "+f"(d[2]), "+f"(d[3])
        : "r"(a[0]), "r"(a[1]), "r"(a[2]), "r"(a[3]),
          "r"(b[0]), "r"(b[1]));
}

__device__ __forceinline__ void ldm_x4(uint32_t* r, uint32_t addr) {
    asm volatile("ldmatrix.sync.aligned.m8n8.x4.shared.b16 {%0,%1,%2,%3}, [%4];"
        : "=r"(r[0]), "=r"(r[1]), "=r"(r[2]), "=r"(r[3]) : "r"(addr));
}
__device__ __forceinline__ void ldm_x4t(uint32_t* r, uint32_t addr) {
    asm volatile("ldmatrix.sync.aligned.m8n8.x4.trans.shared.b16 {%0,%1,%2,%3}, [%4];"
        : "=r"(r[0]), "=r"(r[1]), "=r"(r[2]), "=r"(r[3]) : "r"(addr));
}

__device__ __forceinline__ void cpasync16(uint32_t saddr, const void* g) {
    asm volatile("cp.async.cg.shared.global [%0], [%1], 16;" :: "r"(saddr), "l"(g));
}
#define CP_COMMIT() asm volatile("cp.async.commit_group;" ::: "memory")
#define CP_WAIT0()  asm volatile("cp.async.wait_group 0;" ::: "memory")

// ================= bf16x3 GEMM body, 128x128 tiles =======================
#define WSTR 20
#define CH_WORDS (128 * WSTR)
#define GEMM_SMEM_BYTES (2 * 4 * CH_WORDS * 4)   // 81920

// EPI: 0 fp32 | 2 packed+relu | 3 relu+scatter | 4 relu+dot->atomic | 5 qkv planes
template <int EPI>
__device__ __forceinline__ void gemm_body(
    const uint32_t* __restrict__ Ahi, const uint32_t* __restrict__ Alo,
    const uint32_t* __restrict__ Bhi, const uint32_t* __restrict__ Blo,
    const float* __restrict__ bias,
    float* __restrict__ C, uint32_t* __restrict__ Chi, uint32_t* __restrict__ Clo,
    const void* __restrict__ ei, const float* __restrict__ w2,
    int N, int K, int bm, int bn, uint32_t sb)
{
    const int tid  = threadIdx.x;
    const int lane = tid & 31;
    const int wid  = tid >> 5;
    const int wm64 = (wid >> 2) << 6;
    const int wn32 = (wid & 3) << 5;
    const int Kw = K >> 1;
    const int NKC = K >> 5;

    float acc[4][4][4];
#pragma unroll
    for (int mt = 0; mt < 4; mt++)
#pragma unroll
        for (int nt = 0; nt < 4; nt++)
#pragma unroll
            for (int c = 0; c < 4; c++) acc[mt][nt][c] = 0.f;

    auto stage = [&](int kc, int buf) {
        const uint32_t base = (uint32_t)buf * (4 * CH_WORDS);
        const int kcw = kc << 4;
#pragma unroll
        for (int j = 0; j < 2; j++) {
            int idx = tid + (j << 8);
            int r = idx >> 2, w4 = (idx & 3) << 2;
            uint32_t so = base + (uint32_t)(r * WSTR + w4);
            size_t ga = (size_t)(bm + r) * Kw + kcw + w4;
            size_t gb = (size_t)(bn + r) * Kw + kcw + w4;
            cpasync16(sb + (so << 2),                  Ahi + ga);
            cpasync16(sb + ((so + CH_WORDS) << 2),     Alo + ga);
            cpasync16(sb + ((so + 2 * CH_WORDS) << 2), Bhi + gb);
            cpasync16(sb + ((so + 3 * CH_WORDS) << 2), Blo + gb);
        }
    };

    stage(0, 0);
    CP_COMMIT();

    for (int kc = 0; kc < NKC; kc++) {
        CP_WAIT0();
        __syncthreads();
        if (kc + 1 < NKC) {
            stage(kc + 1, (kc + 1) & 1);
            CP_COMMIT();
        }
        const uint32_t bb = (uint32_t)(kc & 1) * (4 * CH_WORDS);
#pragma unroll
        for (int ks = 0; ks < 2; ks++) {
            const int kw = ks << 3;
            uint32_t ahi[4][4], alo[4][4];
#pragma unroll
            for (int mt = 0; mt < 4; mt++) {
                uint32_t wo = bb + (uint32_t)((wm64 + (mt << 4) + (lane & 15)) * WSTR
                                              + kw + ((lane >> 4) << 2));
                ldm_x4(ahi[mt], sb + (wo << 2));
                ldm_x4(alo[mt], sb + ((wo + CH_WORDS) << 2));
            }
            uint32_t bhi[4][2], blo[4][2];
#pragma unroll
            for (int np = 0; np < 2; np++) {
                uint32_t wo = bb + (uint32_t)((wn32 + (np << 4) + (((lane >> 4) & 1) << 3)
                                               + (lane & 7)) * WSTR
                                              + kw + (((lane >> 3) & 1) << 2));
                uint32_t r4[4];
                ldm_x4(r4, sb + ((wo + 2 * CH_WORDS) << 2));
                bhi[2 * np][0] = r4[0]; bhi[2 * np][1] = r4[1];
                bhi[2 * np + 1][0] = r4[2]; bhi[2 * np + 1][1] = r4[3];
                ldm_x4(r4, sb + ((wo + 3 * CH_WORDS) << 2));
                blo[2 * np][0] = r4[0]; blo[2 * np][1] = r4[1];
                blo[2 * np + 1][0] = r4[2]; blo[2 * np + 1][1] = r4[3];
            }
#pragma unroll
            for (int mt = 0; mt < 4; mt++)
#pragma unroll
                for (int nt = 0; nt < 4; nt++)
                    mma_bf16(acc[mt][nt], ahi[mt], bhi[nt]);
#pragma unroll
            for (int mt = 0; mt < 4; mt++)
#pragma unroll
                for (int nt = 0; nt < 4; nt++)
                    mma_bf16(acc[mt][nt], ahi[mt], blo[nt]);
#pragma unroll
            for (int mt = 0; mt < 4; mt++)
#pragma unroll
                for (int nt = 0; nt < 4; nt++)
                    mma_bf16(acc[mt][nt], alo[mt], bhi[nt]);
        }
    }

    uint32_t *DH = nullptr, *DL = nullptr;
    float epi5_scale = 1.f;
    int epi5_head = 0;
    if (EPI == 5) {
        int which = bn >> 9;
        epi5_head = (bn >> 7) & 3;
        DH = (which == 0) ? g_qhi : (which == 1) ? g_khi : g_vhi;
        DL = (which == 0) ? g_qlo : (which == 1) ? g_klo : g_vlo;
        if (which == 0) epi5_scale = 0.08838834764831845f;
    }

#pragma unroll
    for (int mt = 0; mt < 4; mt++) {
        int row0 = bm + wm64 + (mt << 4) + (lane >> 2);
        int dst0 = 0, dst1 = 0;
        if (EPI == 3) {
            if (g_idx64_flag) {
                dst0 = (int)((const long long*)ei)[E_N + row0];
                dst1 = (int)((const long long*)ei)[E_N + row0 + 8];
            } else {
                dst0 = ((const int*)ei)[E_N + row0];
                dst1 = ((const int*)ei)[E_N + row0 + 8];
            }
            if ((unsigned)dst0 >= (unsigned)E_N) dst0 = 0;
            if ((unsigned)dst1 >= (unsigned)E_N) dst1 = 0;
        }
        float prow0 = 0.f, prow1 = 0.f;
#pragma unroll
        for (int nt = 0; nt < 4; nt++) {
            int col0 = bn + wn32 + (nt << 3) + ((lane & 3) << 1);
            float b0 = bias[col0], b1 = bias[col0 + 1];
            float v00 = acc[mt][nt][0] + b0, v01 = acc[mt][nt][1] + b1;
            float v10 = acc[mt][nt][2] + b0, v11 = acc[mt][nt][3] + b1;
            if (EPI >= 1 && EPI != 5) {
                v00 = fmaxf(v00, 0.f); v01 = fmaxf(v01, 0.f);
                v10 = fmaxf(v10, 0.f); v11 = fmaxf(v11, 0.f);
            }
            if (EPI == 5) {
                v00 *= epi5_scale; v01 *= epi5_scale;
                v10 *= epi5_scale; v11 *= epi5_scale;
                int dw = (col0 & 127) >> 1;
                size_t d0 = ((size_t)epi5_head * E_N + row0) * 64 + dw;
                uint32_t h, l;
                pack2(v00, v01, h, l);
                DH[d0] = h; DL[d0] = l;
                pack2(v10, v11, h, l);
                DH[d0 + 8 * 64] = h; DL[d0 + 8 * 64] = l;
            } else if (EPI == 4) {
                float w0 = w2[col0], w1 = w2[col0 + 1];
                prow0 += v00 * w0 + v01 * w1;
                prow1 += v10 * w0 + v11 * w1;
            } else if (EPI == 3) {
                float* a0 = g_agg + (size_t)dst0 * H_N + col0;
                float* a1 = g_agg + (size_t)dst1 * H_N + col0;
                atomicAdd(a0,     v00); atomicAdd(a0 + 1, v01);
                atomicAdd(a1,     v10); atomicAdd(a1 + 1, v11);
            } else if (EPI == 2) {
                int Nw = N >> 1;
                uint32_t h, l;
                pack2(v00, v01, h, l);
                Chi[(size_t)row0 * Nw + (col0 >> 1)] = h;
                Clo[(size_t)row0 * Nw + (col0 >> 1)] = l;
                pack2(v10, v11, h, l);
                Chi[(size_t)(row0 + 8) * Nw + (col0 >> 1)] = h;
                Clo[(size_t)(row0 + 8) * Nw + (col0 >> 1)] = l;
            } else {
                *(float2*)(C + (size_t)row0 * N + col0) = make_float2(v00, v01);
                *(float2*)(C + (size_t)(row0 + 8) * N + col0) = make_float2(v10, v11);
            }
        }
        if (EPI == 4) {
            prow0 += __shfl_xor_sync(0xffffffffu, prow0, 1);
            prow0 += __shfl_xor_sync(0xffffffffu, prow0, 2);
            prow1 += __shfl_xor_sync(0xffffffffu, prow1, 1);
            prow1 += __shfl_xor_sync(0xffffffffu, prow1, 2);
            if ((lane & 3) == 0) {
                atomicAdd(C + row0, prow0);
                atomicAdd(C + row0 + 8, prow1);
            }
        }
    }
}

template <int EPI>
__global__ __launch_bounds__(256, 2) void gemm_pk(
    const uint32_t* __restrict__ Ahi, const uint32_t* __restrict__ Alo,
    const uint32_t* __restrict__ Bhi, const uint32_t* __restrict__ Blo,
    const float* __restrict__ bias,
    float* __restrict__ C, uint32_t* __restrict__ Chi, uint32_t* __restrict__ Clo,
    const void* __restrict__ ei, const float* __restrict__ w2, int N, int K)
{
    extern __shared__ uint32_t smw[];
    gemm_body<EPI>(Ahi, Alo, Bhi, Blo, bias, C, Chi, Clo, ei, w2, N, K,
                   blockIdx.y << 7, blockIdx.x << 7, smem_u32(smw));
}

__global__ __launch_bounds__(256, 2) void gemm_dual(
    const uint32_t* __restrict__ Ahi, const uint32_t* __restrict__ Alo,
    const uint32_t* __restrict__ B1hi, const uint32_t* __restrict__ B1lo,
    const float* __restrict__ bias1, float* __restrict__ C1,
    const uint32_t* __restrict__ B2hi, const uint32_t* __restrict__ B2lo,
    const float* __restrict__ bias2, const void* __restrict__ ei, int K)
{
    extern __shared__ uint32_t smw[];
    const uint32_t sb = smem_u32(smw);
    const int bm = blockIdx.y << 7;
    if (blockIdx.x < 12)
        gemm_body<0>(Ahi, Alo, B1hi, B1lo, bias1, C1, nullptr, nullptr, nullptr, nullptr,
                     H3_N, K, bm, blockIdx.x << 7, sb);
    else
        gemm_body<3>(Ahi, Alo, B2hi, B2lo, bias2, nullptr, nullptr, nullptr, ei, nullptr,
                     H_N, K, bm, (blockIdx.x - 12) << 7, sb);
}

// ---------------- prep ----------------
// blocks: [0,1792) weights | [1792,2816) x | [2816,4864) zero agg v4 | [4864,4880) out
__global__ __launch_bounds__(256) void prep_kernel(
    const float* __restrict__ x, const int* __restrict__ ei32,
    const float* __restrict__ w0, const float* __restrict__ w1,
    const float* __restrict__ w2, const float* __restrict__ w3,
    const float* __restrict__ w4, const float* __restrict__ w5,
    const float* __restrict__ w6,
    float* __restrict__ out, const float* __restrict__ b2)
{
    int b = blockIdx.x;
    if (b < 1792) {
        int i = b * 256 + threadIdx.x;
        const unsigned char segtab[14] = {0,1,1,1,2,2,2,3,3,3,4,5,6,6};
        const int segbase[7] = {0, 32768, 131072, 229376, 327680, 360448, 393216};
        int unit = i >> 15;
        int seg = segtab[unit];
        int li = i - segbase[seg];
        const float* src;
        switch (seg) {
            case 0: src = w0; break;
            case 1: src = w1; break;
            case 2: src = w2; break;
            case 3: src = w3; break;
            case 4: src = w4; break;
            case 5: src = w5; break;
            default: src = w6; break;
        }
        float4 a = *(const float4*)(src + (size_t)li * 8);
        float4 c = *(const float4*)(src + (size_t)li * 8 + 4);
        uint4 h, l;
        pack2(a.x, a.y, h.x, l.x);
        pack2(a.z, a.w, h.y, l.y);
        pack2(c.x, c.y, h.z, l.z);
        pack2(c.z, c.w, h.w, l.w);
        *(uint4*)(g_whi + (size_t)i * 4) = h;
        *(uint4*)(g_wlo + (size_t)i * 4) = l;
    } else if (b < 2816) {
        int i = (b - 1792) * 256 + threadIdx.x;
        float4 a = *(const float4*)(x + (size_t)i * 8);
        float4 c = *(const float4*)(x + (size_t)i * 8 + 4);
        uint4 h, l;
        pack2(a.x, a.y, h.x, l.x);
        pack2(a.z, a.w, h.y, l.y);
        pack2(c.x, c.y, h.z, l.z);
        pack2(c.z, c.w, h.w, l.w);
        *(uint4*)(g_xhi + (size_t)i * 4) = h;
        *(uint4*)(g_xlo + (size_t)i * 4) = l;
    } else if (b < 4864) {
        int i = (b - 2816) * 256 + threadIdx.x;
        *(float4*)(g_agg + (size_t)i * 4) = make_float4(0.f, 0.f, 0.f, 0.f);
        if (i == 0) {
            int allzero = 1;
#pragma unroll
            for (int k = 1; k < 16; k += 2)
                if (ei32[k] != 0) allzero = 0;
            g_idx64_flag = allzero;
        }
    } else {
        int i = (b - 4864) * 256 + threadIdx.x;
        out[i] = b2[0];
    }
}

// ---------------- vectorized pair-split (agg) ----------------
__global__ __launch_bounds__(256) void split_pairs_v4(
    const float* __restrict__ src, uint32_t* __restrict__ hi,
    uint32_t* __restrict__ lo, int ngroups)
{
    int i = blockIdx.x * 256 + threadIdx.x;
    if (i >= ngroups) return;
    float4 a = *(const float4*)(src + (size_t)i * 8);
    float4 b = *(const float4*)(src + (size_t)i * 8 + 4);
    uint4 h, l;
    pack2(a.x, a.y, h.x, l.x);
    pack2(a.z, a.w, h.y, l.y);
    pack2(b.x, b.y, h.z, l.z);
    pack2(b.z, b.w, h.w, l.w);
    *(uint4*)(hi + (size_t)i * 4) = h;
    *(uint4*)(lo + (size_t)i * 4) = l;
}

// ---------------- GRU elementwise (+ h planes) ----------------
__global__ __launch_bounds__(256) void gru_kernel(const float* __restrict__ x) {
    int idx = blockIdx.x * 256 + threadIdx.x;
    if (idx >= E_N * 256) return;
    int e = idx >> 8, i = (idx & 255) << 1;
    const float* gi = g_gi + (size_t)e * H3_N;
    const float* gh = g_gh + (size_t)e * H3_N;
    float h2[2];
#pragma unroll
    for (int u = 0; u < 2; u++) {
        int c = i + u;
        float r = 1.f / (1.f + __expf(-(gi[c] + gh[c])));
        float z = 1.f / (1.f + __expf(-(gi[H_N + c] + gh[H_N + c])));
        float n = tanhf(gi[2 * H_N + c] + r * gh[2 * H_N + c]);
        h2[u] = (1.f - z) * n + z * x[(size_t)e * H_N + c];
        g_h[(size_t)e * H_N + c] = h2[u];
    }
    uint32_t h, l;
    pack2(h2[0], h2[1], h, l);
    g_hhi[idx] = h; g_hlo[idx] = l;
}

// ---------------- flash-attention: reg softmax, cp.async KV, trans-V -----
// 128 q-rows, 256 threads (8 warps), BC=64 (R15 proven config)
#define ATQ_STR 68
#define ATQ_WORDS (128 * ATQ_STR)          // 8704 per plane
#define ATK_WORDS (64 * ATQ_STR)           // 4352 per plane (K and V)
#define AT_KV0 (2 * ATQ_WORDS)             // 17408
#define KVBUF_WORDS (4 * ATK_WORDS)        // 17408
#define ATTN_SMEM_BYTES ((AT_KV0 + 2 * KVBUF_WORDS) * 4)  // 208896

__global__ __launch_bounds__(256) void attn_bf16_kernel() {
    extern __shared__ uint32_t smw[];
    const uint32_t sb = smem_u32(smw);

    const int t = threadIdx.x;
    const int lane = t & 31;
    const int w = t >> 5;
    const int q0 = blockIdx.x << 7;
    const int head = blockIdx.y;

    {
        size_t qb = ((size_t)head * E_N + q0) * 64;
#pragma unroll
        for (int j = 0; j < 8; j++) {
            int i = t + (j << 8);
            int r = i >> 4, w4 = (i & 15) << 2;
            *(uint4*)(smw + r * ATQ_STR + w4) = *(const uint4*)&g_qhi[qb + r * 64 + w4];
            *(uint4*)(smw + ATQ_WORDS + r * ATQ_STR + w4) = *(const uint4*)&g_qlo[qb + r * 64 + w4];
        }
    }

    auto stage_kv = [&](int j0, int buf) {
        const uint32_t base = AT_KV0 + (uint32_t)buf * KVBUF_WORDS;
        size_t kb = ((size_t)head * E_N + j0) * 64;
#pragma unroll
        for (int j = 0; j < 4; j++) {
            int i = t + (j << 8);
            int r = i >> 4, w4 = (i & 15) << 2;
            uint32_t so = base + (uint32_t)(r * ATQ_STR + w4);
            cpasync16(sb + (so << 2),                   g_khi + kb + r * 64 + w4);
            cpasync16(sb + ((so + ATK_WORDS) << 2),     g_klo + kb + r * 64 + w4);
            cpasync16(sb + ((so + 2 * ATK_WORDS) << 2), g_vhi + kb + r * 64 + w4);
            cpasync16(sb + ((so + 3 * ATK_WORDS) << 2), g_vlo + kb + r * 64 + w4);
        }
    };

    stage_kv(0, 0);
    CP_COMMIT();

    float o[16][4];
#pragma unroll
    for (int nf = 0; nf < 16; nf++)
#pragma unroll
        for (int c = 0; c < 4; c++) o[nf][c] = 0.f;
    float m0 = -1e30f, m1 = -1e30f, l0 = 0.f, l1 = 0.f;

    int buf = 0;
    for (int j0 = 0; j0 < E_N; j0 += 64) {
        CP_WAIT0();
        __syncthreads();
        if (j0 + 64 < E_N) {
            stage_kv(j0 + 64, buf ^ 1);
            CP_COMMIT();
        }
        const uint32_t kvb = AT_KV0 + (uint32_t)buf * KVBUF_WORDS;

        // ---- S = Q K^T ----
        float sacc[8][4];
#pragma unroll
        for (int nf = 0; nf < 8; nf++)
#pragma unroll
            for (int c = 0; c < 4; c++) sacc[nf][c] = 0.f;

#pragma unroll
        for (int ks = 0; ks < 8; ks++) {
            const int kw = ks << 3;
            uint32_t ahi[4], alo[4];
            uint32_t ao = (uint32_t)((((w << 4) + (lane & 15)) * ATQ_STR
                                      + kw + ((lane >> 4) << 2)) << 2);
            ldm_x4(ahi, sb + ao);
            ldm_x4(alo, sb + ao + (ATQ_WORDS << 2));
#pragma unroll
            for (int np = 0; np < 4; np++) {
                uint32_t bo = (uint32_t)((kvb + ((np << 4) + (((lane >> 4) & 1) << 3)
                                                 + (lane & 7)) * ATQ_STR
                                          + kw + (((lane >> 3) & 1) << 2)) << 2);
                uint32_t bh4[4], bl4[4];
                ldm_x4(bh4, sb + bo);
                ldm_x4(bl4, sb + bo + (ATK_WORDS << 2));
                mma_bf16(sacc[2 * np],     ahi, bh4);
                mma_bf16(sacc[2 * np],     ahi, bl4);
                mma_bf16(sacc[2 * np],     alo, bh4);
                mma_bf16(sacc[2 * np + 1], ahi, bh4 + 2);
                mma_bf16(sacc[2 * np + 1], ahi, bl4 + 2);
                mma_bf16(sacc[2 * np + 1], alo, bh4 + 2);
            }
        }

        // ---- register online softmax ----
        float mloc0 = -1e30f, mloc1 = -1e30f;
#pragma unroll
        for (int nf = 0; nf < 8; nf++) {
            mloc0 = fmaxf(mloc0, fmaxf(sacc[nf][0], sacc[nf][1]));
            mloc1 = fmaxf(mloc1, fmaxf(sacc[nf][2], sacc[nf][3]));
        }
        mloc0 = fmaxf(mloc0, __shfl_xor_sync(0xffffffffu, mloc0, 1));
        mloc0 = fmaxf(mloc0, __shfl_xor_sync(0xffffffffu, mloc0, 2));
        mloc1 = fmaxf(mloc1, __shfl_xor_sync(0xffffffffu, mloc1, 1));
        mloc1 = fmaxf(mloc1, __shfl_xor_sync(0xffffffffu, mloc1, 2));
        float mnew0 = fmaxf(m0, mloc0), mnew1 = fmaxf(m1, mloc1);
        float alpha0 = __expf(m0 - mnew0), alpha1 = __expf(m1 - mnew1);
        float s0 = 0.f, s1 = 0.f;
#pragma unroll
        for (int nf = 0; nf < 8; nf++) {
            sacc[nf][0] = __expf(sacc[nf][0] - mnew0);
            sacc[nf][1] = __expf(sacc[nf][1] - mnew0);
            sacc[nf][2] = __expf(sacc[nf][2] - mnew1);
            sacc[nf][3] = __expf(sacc[nf][3] - mnew1);
            s0 += sacc[nf][0] + sacc[nf][1];
            s1 += sacc[nf][2] + sacc[nf][3];
        }
        s0 += __shfl_xor_sync(0xffffffffu, s0, 1);
        s0 += __shfl_xor_sync(0xffffffffu, s0, 2);
        s1 += __shfl_xor_sync(0xffffffffu, s1, 1);
        s1 += __shfl_xor_sync(0xffffffffu, s1, 2);
        l0 = l0 * alpha0 + s0;  m0 = mnew0;
        l1 = l1 * alpha1 + s1;  m1 = mnew1;
#pragma unroll
        for (int nf = 0; nf < 16; nf++) {
            o[nf][0] *= alpha0; o[nf][1] *= alpha0;
            o[nf][2] *= alpha1; o[nf][3] *= alpha1;
        }

        // ---- O += P V; V frags via trans ldmatrix from natural layout ----
#pragma unroll
        for (int ks = 0; ks < 4; ks++) {
            uint32_t phi[4], plo[4];
            pack2(sacc[2 * ks][0],     sacc[2 * ks][1],     phi[0], plo[0]);
            pack2(sacc[2 * ks][2],     sacc[2 * ks][3],     phi[1], plo[1]);
            pack2(sacc[2 * ks + 1][0], sacc[2 * ks + 1][1], phi[2], plo[2]);
            pack2(sacc[2 * ks + 1][2], sacc[2 * ks + 1][3], phi[3], plo[3]);
#pragma unroll
            for (int np = 0; np < 8; np++) {
                uint32_t bo = (uint32_t)((kvb + 2 * ATK_WORDS
                                          + ((ks << 4) + (lane & 15)) * ATQ_STR
                                          + (np << 3) + ((lane >> 4) << 2)) << 2);
                uint32_t bh4[4], bl4[4];
                ldm_x4t(bh4, sb + bo);
                ldm_x4t(bl4, sb + bo + (ATK_WORDS << 2));
                mma_bf16(o[2 * np],     phi, bh4);
                mma_bf16(o[2 * np],     phi, bl4);
                mma_bf16(o[2 * np],     plo, bh4);
                mma_bf16(o[2 * np + 1], phi, bh4 + 2);
                mma_bf16(o[2 * np + 1], phi, bl4 + 2);
                mma_bf16(o[2 * np + 1], plo, bh4 + 2);
            }
        }
        buf ^= 1;
    }

    // ---- epilogue ----
    {
        const int gid = lane >> 2;
        const int qid = lane & 3;
        const int r0 = (w << 4) + gid;
        float inv0 = 1.f / l0;
        float inv1 = 1.f / l1;
#pragma unroll
        for (int nf = 0; nf < 16; nf++) {
            int cw = head * 64 + (nf << 2) + qid;
            uint32_t h, l;
            pack2(o[nf][0] * inv0, o[nf][1] * inv0, h, l);
            g_attnhi[(size_t)(q0 + r0) * 256 + cw] = h;
            g_attnlo[(size_t)(q0 + r0) * 256 + cw] = l;
            pack2(o[nf][2] * inv1, o[nf][3] * inv1, h, l);
            g_attnhi[(size_t)(q0 + r0 + 8) * 256 + cw] = h;
            g_attnlo[(size_t)(q0 + r0 + 8) * 256 + cw] = l;
        }
    }
}

// ---------------- residual + LayerNorm ----------------
__global__ __launch_bounds__(256) void ln_kernel(const float* __restrict__ ln_g,
                                                 const float* __restrict__ ln_b) {
    __shared__ float reda[8], redb[8];
    int e = blockIdx.x;
    int t = threadIdx.x;
    const float* yp = g_yprj + (size_t)e * H_N;
    const float* hp = g_h + (size_t)e * H_N;
    int i0 = t << 1, i1 = i0 + 1;
    float v0 = yp[i0] + hp[i0];
    float v1 = yp[i1] + hp[i1];
    float s = v0 + v1, s2 = v0 * v0 + v1 * v1;
#pragma unroll
    for (int o = 16; o > 0; o >>= 1) {
        s  += __shfl_down_sync(0xffffffffu, s, o);
        s2 += __shfl_down_sync(0xffffffffu, s2, o);
    }
    int w = t >> 5;
    if ((t & 31) == 0) { reda[w] = s; redb[w] = s2; }
    __syncthreads();
    if (t < 8) {
        s = reda[t]; s2 = redb[t];
#pragma unroll
        for (int o = 4; o > 0; o >>= 1) {
            s  += __shfl_down_sync(0xffu, s, o);
            s2 += __shfl_down_sync(0xffu, s2, o);
        }
        if (t == 0) { reda[0] = s; redb[0] = s2; }
    }
    __syncthreads();
    float mu = reda[0] * (1.f / H_N);
    float var = redb[0] * (1.f / H_N) - mu * mu;
    float rstd = rsqrtf(var + 1e-5f);
    float y0 = (v0 - mu) * rstd * ln_g[i0] + ln_b[i0];
    float y1 = (v1 - mu) * rstd * ln_g[i1] + ln_b[i1];
    uint32_t h, l;
    pack2(y0, y1, h, l);
    g_ynhi[(size_t)e * 256 + t] = h;
    g_ynlo[(size_t)e * 256 + t] = l;
}

// ---------------- launcher ----------------
extern "C" void kernel_launch(void* const* d_in, const int* in_sizes, int n_in,
                              void* d_out, int out_size) {
    const float* x       = (const float*)d_in[0];
    const void*  ei      = d_in[1];
    const float* W_msg   = (const float*)d_in[2];
    const float* b_msg   = (const float*)d_in[3];
    const float* W_ih    = (const float*)d_in[4];
    const float* b_ih    = (const float*)d_in[5];
    const float* W_hh    = (const float*)d_in[6];
    const float* b_hh    = (const float*)d_in[7];
    const float* W_inp   = (const float*)d_in[8];
    const float* b_inp   = (const float*)d_in[9];
    const float* W_outp  = (const float*)d_in[10];
    const float* b_outp  = (const float*)d_in[11];
    const float* ln_g    = (const float*)d_in[12];
    const float* ln_b    = (const float*)d_in[13];
    const float* W_lin   = (const float*)d_in[14];
    const float* b_lin   = (const float*)d_in[15];
    const float* W_f1    = (const float*)d_in[16];
    const float* b_f1    = (const float*)d_in[17];
    const float* W_f2    = (const float*)d_in[18];
    const float* b_f2    = (const float*)d_in[19];
    float* out = (float*)d_out;

    float *p_gi, *p_gh, *p_yprj, *p_agg;
    cudaGetSymbolAddress((void**)&p_agg,  g_agg);
    cudaGetSymbolAddress((void**)&p_gi,   g_gi);
    cudaGetSymbolAddress((void**)&p_gh,   g_gh);
    cudaGetSymbolAddress((void**)&p_yprj, g_yprj);
    uint32_t *p_xhi, *p_xlo, *p_agghi, *p_agglo, *p_hhi, *p_hlo;
    uint32_t *p_attnhi, *p_attnlo, *p_ynhi, *p_ynlo, *p_gacthi, *p_gactlo;
    uint32_t *p_whi, *p_wlo;
    cudaGetSymbolAddress((void**)&p_xhi,    g_xhi);
    cudaGetSymbolAddress((void**)&p_xlo,    g_xlo);
    cudaGetSymbolAddress((void**)&p_agghi,  g_agghi);
    cudaGetSymbolAddress((void**)&p_agglo,  g_agglo);
    cudaGetSymbolAddress((void**)&p_hhi,    g_hhi);
    cudaGetSymbolAddress((void**)&p_hlo,    g_hlo);
    cudaGetSymbolAddress((void**)&p_attnhi, g_attnhi);
    cudaGetSymbolAddress((void**)&p_attnlo, g_attnlo);
    cudaGetSymbolAddress((void**)&p_ynhi,   g_ynhi);
    cudaGetSymbolAddress((void**)&p_ynlo,   g_ynlo);
    cudaGetSymbolAddress((void**)&p_gacthi, g_gacthi);
    cudaGetSymbolAddress((void**)&p_gactlo, g_gactlo);
    cudaGetSymbolAddress((void**)&p_whi,    g_whi);
    cudaGetSymbolAddress((void**)&p_wlo,    g_wlo);

    cudaFuncSetAttribute(gemm_pk<0>, cudaFuncAttributeMaxDynamicSharedMemorySize, GEMM_SMEM_BYTES);
    cudaFuncSetAttribute(gemm_pk<2>, cudaFuncAttributeMaxDynamicSharedMemorySize, GEMM_SMEM_BYTES);
    cudaFuncSetAttribute(gemm_pk<4>, cudaFuncAttributeMaxDynamicSharedMemorySize, GEMM_SMEM_BYTES);
    cudaFuncSetAttribute(gemm_pk<5>, cudaFuncAttributeMaxDynamicSharedMemorySize, GEMM_SMEM_BYTES);
    cudaFuncSetAttribute(gemm_dual,  cudaFuncAttributeMaxDynamicSharedMemorySize, GEMM_SMEM_BYTES);
    cudaFuncSetAttribute(attn_bf16_kernel, cudaFuncAttributeMaxDynamicSharedMemorySize, ATTN_SMEM_BYTES);

    // 0) prep
    prep_kernel<<<4880, 256>>>(x, (const int*)ei, W_msg, W_ih, W_hh, W_inp,
                               W_outp, W_lin, W_f1, out, b_f2);
    // 1) merged gh + msg(scatter) GEMM
    gemm_dual<<<dim3(16, 32), 256, GEMM_SMEM_BYTES>>>(
        p_xhi, p_xlo,
        p_whi + WOFF_HH, p_wlo + WOFF_HH, b_hh, p_gh,
        p_whi + WOFF_MSG, p_wlo + WOFF_MSG, b_msg, ei, H_N);
    // 2) agg planes
    split_pairs_v4<<<(E_N * 64) / 256, 256>>>(p_agg, p_agghi, p_agglo, E_N * 64);
    // 3) gi   <-- profiled slot
    gemm_pk<0><<<dim3(H3_N / 128, 32), 256, GEMM_SMEM_BYTES>>>(
        p_agghi, p_agglo, p_whi + WOFF_IH, p_wlo + WOFF_IH, b_ih, p_gi,
        nullptr, nullptr, nullptr, nullptr, H3_N, H_N);
    // 4) GRU
    gru_kernel<<<(E_N * 256) / 256, 256>>>(x);
    // 5) qkv -> per-head Q/K/V planes (EPI5)
    gemm_pk<5><<<dim3(H3_N / 128, 32), 256, GEMM_SMEM_BYTES>>>(
        p_hhi, p_hlo, p_whi + WOFF_INP, p_wlo + WOFF_INP, b_inp, nullptr,
        nullptr, nullptr, nullptr, nullptr, H3_N, H_N);
    // 6) attention (128-row CTAs, R15 config)
    attn_bf16_kernel<<<dim3(E_N / 128, NH_N), 256, ATTN_SMEM_BYTES>>>();
    // 7) out-proj
    gemm_pk<0><<<dim3(H_N / 128, 32), 256, GEMM_SMEM_BYTES>>>(
        p_attnhi, p_attnlo, p_whi + WOFF_OUTP, p_wlo + WOFF_OUTP, b_outp, p_yprj,
        nullptr, nullptr, nullptr, nullptr, H_N, H_N);
    // 8) residual + LN
    ln_kernel<<<E_N, 256>>>(ln_g, ln_b);
    // 9) g = relu(yn @ W_lin^T + b) -> packed
    gemm_pk<2><<<dim3(H_N / 128, 32), 256, GEMM_SMEM_BYTES>>>(
        p_ynhi, p_ynlo, p_whi + WOFF_LIN, p_wlo + WOFF_LIN, b_lin, nullptr,
        p_gacthi, p_gactlo, nullptr, nullptr, H_N, H_N);
    // 10) f = relu(g @ W_f1^T + b_f1) fused with final dot
    gemm_pk<4><<<dim3(FFN_N / 128, 32), 256, GEMM_SMEM_BYTES>>>(
        p_gacthi, p_gactlo, p_whi + WOFF_F1, p_wlo + WOFF_F1, b_f1, out,
        nullptr, nullptr, nullptr, W_f2, FFN_N, H_N);
}